// round 2
// baseline (speedup 1.0000x reference)
#include <cuda_runtime.h>
#include <cstdint>

// ---------------------------------------------------------------------------
// Family-portable sm_103 kernel: tf32 mma.sync + cp.async double buffering.
// (tcgen05/TMA-tensor are sm_103a-gated PTX; the harness emits compute_103.)
// ---------------------------------------------------------------------------

static constexpr int BATCH = 65536;
static constexpr int DH = 512;   // d_hidden
static constexpr int DI = 128;   // d_in
static constexpr int DO = 128;   // d_out
static constexpr int BM = 128;   // batch rows per CTA
static constexpr int NT = 256;   // threads (8 warps)
static constexpr int NCH = 8;    // h-chunks of 64

// SMEM float offsets
static constexpr int U_OFF  = 0;      // u tile  [128m x 128k] tf32 (64KB)
static constexpr int B_OFF0 = 16384;  // b chunk [128k x 64n]  (32KB) buf0
static constexpr int B_OFF1 = 24576;  //                        buf1
static constexpr int C_OFF0 = 32768;  // c chunk [64k x 128n]  (32KB) buf0
static constexpr int C_OFF1 = 40960;  //                        buf1
static constexpr int XN_OFF = 49152;  // x_new stage [128m x 64k] (32KB)
static constexpr int DEC_OFF = 57344; // decay[512]
static constexpr int SMEM_BYTES = 57856 * 4;  // 231424 B

__device__ __forceinline__ uint32_t f2tf(float f) {
    uint32_t r;
    asm("cvt.rna.tf32.f32 %0, %1;" : "=r"(r) : "f"(f));
    return r;
}
__device__ __forceinline__ uint32_t smem_u32(const void* p) {
    uint32_t a;
    asm("{ .reg .u64 t; cvta.to.shared.u64 t, %1; cvt.u32.u64 %0, t; }" : "=r"(a) : "l"(p));
    return a;
}
__device__ __forceinline__ void cpa16(uint32_t d, const void* s) {
    asm volatile("cp.async.cg.shared.global [%0], [%1], 16;" :: "r"(d), "l"(s));
}
#define CP_COMMIT() asm volatile("cp.async.commit_group;" ::: "memory")
#define CP_WAIT(n)  asm volatile("cp.async.wait_group %0;" :: "n"(n) : "memory")

// D += A(m16k8) * B(k8n8), tf32 operands, f32 accum
__device__ __forceinline__ void mma8(float* c, const uint32_t* a, uint32_t b0, uint32_t b1) {
    asm volatile(
        "mma.sync.aligned.m16n8k8.row.col.f32.tf32.tf32.f32 "
        "{%0,%1,%2,%3}, {%4,%5,%6,%7}, {%8,%9}, {%0,%1,%2,%3};"
        : "+f"(c[0]), "+f"(c[1]), "+f"(c[2]), "+f"(c[3])
        : "r"(a[0]), "r"(a[1]), "r"(a[2]), "r"(a[3]), "r"(b0), "r"(b1));
}

__global__ void __launch_bounds__(NT, 1)
rnn_kernel(const float* __restrict__ X, const float* __restrict__ U,
           const float* __restrict__ A, const float* __restrict__ B,
           const float* __restrict__ C, float* __restrict__ OUT) {
    extern __shared__ float sm[];
    const int tid = threadIdx.x, wid = tid >> 5, lid = tid & 31;
    const int q = lid & 3, r = lid >> 2;
    const int row0 = (int)blockIdx.x * BM;
    const uint32_t smb = smem_u32(sm);

    // ---- issue cp.async: U tile (group 0) ----
    {
        const float* ug = U + (size_t)row0 * DI;
        for (int i = tid; i < 4096; i += NT) {
            int m = i >> 5, j = i & 31;
            uint32_t dst = smb + (uint32_t)(U_OFF + m * 128 + ((j ^ (m & 7)) << 2)) * 4u;
            cpa16(dst, ug + m * DI + 4 * j);
        }
        CP_COMMIT();
    }
    // ---- issue cp.async: b/c chunks 0 and 1 (groups 1, 2) ----
    #pragma unroll
    for (int pf = 0; pf < 2; ++pf) {
        const int hb = pf * 64;
        const int bo = pf ? B_OFF1 : B_OFF0, co = pf ? C_OFF1 : C_OFF0;
        for (int i = tid; i < 2048; i += NT) {  // b chunk: [k=128][n=64]
            int k = i >> 4, j = i & 15;
            uint32_t dst = smb + (uint32_t)(bo + k * 64 + ((j ^ ((k & 3) << 1)) << 2)) * 4u;
            cpa16(dst, B + (size_t)k * DH + hb + 4 * j);
        }
        for (int i = tid; i < 2048; i += NT) {  // c chunk: [h=64][n=128]
            int h = i >> 5, j = i & 31;
            uint32_t dst = smb + (uint32_t)(co + h * 128 + ((j ^ ((h & 3) << 1)) << 2)) * 4u;
            cpa16(dst, C + (size_t)(hb + h) * DO + 4 * j);
        }
        CP_COMMIT();
    }

    // ---- softmax(a) -> dec[512]  (overlaps in-flight cp.async) ----
    {
        float* red = sm + XN_OFF;  // reuse x_new stage as scratch
        float a0 = A[tid], a1 = A[tid + NT];
        red[tid] = fmaxf(a0, a1);
        __syncthreads();
        for (int o = 128; o > 0; o >>= 1) {
            if (tid < o) red[tid] = fmaxf(red[tid], red[tid + o]);
            __syncthreads();
        }
        float mx = red[0];
        __syncthreads();
        float e0 = expf(a0 - mx), e1 = expf(a1 - mx);
        red[tid] = e0 + e1;
        __syncthreads();
        for (int o = 128; o > 0; o >>= 1) {
            if (tid < o) red[tid] += red[tid + o];
            __syncthreads();
        }
        float inv = 1.0f / red[0];
        __syncthreads();
        sm[DEC_OFF + tid] = e0 * inv;
        sm[DEC_OFF + NT + tid] = e1 * inv;
    }

    // ---- convert U to tf32 in place ----
    CP_WAIT(2);
    __syncthreads();
    for (int i = tid * 4; i < 16384; i += NT * 4) {
        float4 v = *(float4*)&sm[U_OFF + i];
        uint4 w = make_uint4(f2tf(v.x), f2tf(v.y), f2tf(v.z), f2tf(v.w));
        *(uint4*)&sm[U_OFF + i] = w;
    }

    // persistent output accumulator [2 mtiles][8 ntiles][4]
    float acc2[2][8][4];
    #pragma unroll
    for (int a = 0; a < 2; ++a)
        #pragma unroll
        for (int b2 = 0; b2 < 8; ++b2)
            #pragma unroll
            for (int c2 = 0; c2 < 4; ++c2) acc2[a][b2][c2] = 0.f;

    const int mb1 = (wid >> 1) * 32, nb1 = (wid & 1) * 32;   // GEMM1 warp tile 32x32
    const int mb2 = (wid >> 1) * 32, nb2 = (wid & 1) * 64;   // GEMM2 warp tile 32x64

    for (int ch = 0; ch < NCH; ++ch) {
        const int cur = ch & 1;
        const int bo = cur ? B_OFF1 : B_OFF0, co = cur ? C_OFF1 : C_OFF0;
        const int hbase = ch * 64;

        CP_WAIT(1);
        __syncthreads();
        // convert this chunk's b and c to tf32 in place
        for (int i = tid * 4; i < 8192; i += NT * 4) {
            float4 v = *(float4*)&sm[bo + i];
            *(uint4*)&sm[bo + i] = make_uint4(f2tf(v.x), f2tf(v.y), f2tf(v.z), f2tf(v.w));
            float4 v2 = *(float4*)&sm[co + i];
            *(uint4*)&sm[co + i] = make_uint4(f2tf(v2.x), f2tf(v2.y), f2tf(v2.z), f2tf(v2.w));
        }
        __syncthreads();

        // ---- GEMM1: T1[128 x 64] = u[128x128] @ b_chunk[128x64] ----
        float acc1[2][4][4];
        #pragma unroll
        for (int a = 0; a < 2; ++a)
            #pragma unroll
            for (int b2 = 0; b2 < 4; ++b2)
                #pragma unroll
                for (int c2 = 0; c2 < 4; ++c2) acc1[a][b2][c2] = 0.f;

        {
            const uint32_t* su = (const uint32_t*)(sm + U_OFF);
            const uint32_t* sb = (const uint32_t*)(sm + bo);
            #pragma unroll
            for (int ks = 0; ks < 16; ++ks) {
                const int k0 = ks * 8 + q;
                uint32_t af[2][4], bf[4][2];
                #pragma unroll
                for (int tm = 0; tm < 2; ++tm) {
                    const int m = mb1 + tm * 16 + r;
                    const int kx = (m & 7) << 2;  // same for m and m+8
                    af[tm][0] = su[m * 128 + (k0 ^ kx)];
                    af[tm][1] = su[(m + 8) * 128 + (k0 ^ kx)];
                    af[tm][2] = su[m * 128 + ((k0 + 4) ^ kx)];
                    af[tm][3] = su[(m + 8) * 128 + ((k0 + 4) ^ kx)];
                }
                const int nx = (k0 & 3) << 3;  // same for k0 and k0+4
                #pragma unroll
                for (int tn = 0; tn < 4; ++tn) {
                    const int n = nb1 + tn * 8 + r;
                    bf[tn][0] = sb[k0 * 64 + (n ^ nx)];
                    bf[tn][1] = sb[(k0 + 4) * 64 + (n ^ nx)];
                }
                #pragma unroll
                for (int tm = 0; tm < 2; ++tm)
                    #pragma unroll
                    for (int tn = 0; tn < 4; ++tn)
                        mma8(acc1[tm][tn], af[tm], bf[tn][0], bf[tn][1]);
            }
        }

        // ---- epilogue: x_new = T1 + decay*x ; STG ; stage tf32 in SMEM ----
        {
            const float* dec = sm + DEC_OFF + hbase;
            uint32_t* xs = (uint32_t*)(sm + XN_OFF);
            #pragma unroll
            for (int tm = 0; tm < 2; ++tm) {
                #pragma unroll
                for (int half = 0; half < 2; ++half) {
                    const int mloc = mb1 + tm * 16 + half * 8 + r;
                    const size_t grow = (size_t)(row0 + mloc);
                    const float* xr = X + grow * DH + hbase;
                    float* yr = OUT + grow * DH + hbase;
                    const int kx = (mloc & 7) << 2;
                    #pragma unroll
                    for (int tn = 0; tn < 4; ++tn) {
                        const int col = nb1 + tn * 8 + 2 * q;
                        float2 xv = *(const float2*)(xr + col);
                        float2 dv = *(const float2*)(dec + col);
                        float v0 = acc1[tm][tn][half * 2 + 0] + dv.x * xv.x;
                        float v1 = acc1[tm][tn][half * 2 + 1] + dv.y * xv.y;
                        *(float2*)(yr + col) = make_float2(v0, v1);
                        const int idx = mloc * 64 + (col ^ kx);  // col even: pair stays intact
                        *(uint2*)&xs[idx] = make_uint2(f2tf(v0), f2tf(v1));
                    }
                }
            }
        }
        __syncthreads();

        // ---- GEMM2: Out[128x128] += x_new_chunk[128x64] @ c_chunk[64x128] ----
        {
            const uint32_t* sx = (const uint32_t*)(sm + XN_OFF);
            const uint32_t* sc = (const uint32_t*)(sm + co);
            #pragma unroll
            for (int ks = 0; ks < 8; ++ks) {
                const int k0 = ks * 8 + q;
                uint32_t af[2][4];
                #pragma unroll
                for (int tm = 0; tm < 2; ++tm) {
                    const int m = mb2 + tm * 16 + r;
                    const int kx = (m & 7) << 2;
                    af[tm][0] = sx[m * 64 + (k0 ^ kx)];
                    af[tm][1] = sx[(m + 8) * 64 + (k0 ^ kx)];
                    af[tm][2] = sx[m * 64 + ((k0 + 4) ^ kx)];
                    af[tm][3] = sx[(m + 8) * 64 + ((k0 + 4) ^ kx)];
                }
                const int nx = (k0 & 3) << 3;
                #pragma unroll
                for (int tn = 0; tn < 8; ++tn) {
                    const int n = nb2 + tn * 8 + r;
                    uint32_t b0 = sc[k0 * 128 + (n ^ nx)];
                    uint32_t b1 = sc[(k0 + 4) * 128 + (n ^ nx)];
                    mma8(acc2[0][tn], af[0], b0, b1);
                    mma8(acc2[1][tn], af[1], b0, b1);
                }
            }
        }
        __syncthreads();

        // ---- prefetch b/c for chunk ch+2 into the buffer we just freed ----
        if (ch + 2 < NCH) {
            const int hb = (ch + 2) * 64;
            for (int i = tid; i < 2048; i += NT) {
                int k = i >> 4, j = i & 15;
                uint32_t dst = smb + (uint32_t)(bo + k * 64 + ((j ^ ((k & 3) << 1)) << 2)) * 4u;
                cpa16(dst, B + (size_t)k * DH + hb + 4 * j);
            }
            for (int i = tid; i < 2048; i += NT) {
                int h = i >> 5, j = i & 31;
                uint32_t dst = smb + (uint32_t)(co + h * 128 + ((j ^ ((h & 3) << 1)) << 2)) * 4u;
                cpa16(dst, C + (size_t)(hb + h) * DO + 4 * j);
            }
        }
        CP_COMMIT();  // unconditional: keeps per-thread group counting uniform
    }

    // ---- final epilogue: write output GEMM ----
    {
        float* ob = OUT + (size_t)BATCH * DH;
        #pragma unroll
        for (int tm = 0; tm < 2; ++tm) {
            #pragma unroll
            for (int half = 0; half < 2; ++half) {
                const int mloc = mb2 + tm * 16 + half * 8 + r;
                float* orow = ob + (size_t)(row0 + mloc) * DO;
                #pragma unroll
                for (int tn = 0; tn < 8; ++tn) {
                    const int col = nb2 + tn * 8 + 2 * q;
                    *(float2*)(orow + col) =
                        make_float2(acc2[tm][tn][half * 2], acc2[tm][tn][half * 2 + 1]);
                }
            }
        }
    }
}

extern "C" void kernel_launch(void* const* d_in, const int* in_sizes, int n_in,
                              void* d_out, int out_size) {
    const float* x = (const float*)d_in[0];  // [65536, 512]
    const float* u = (const float*)d_in[1];  // [65536, 128]
    const float* a = (const float*)d_in[2];  // [512]
    const float* b = (const float*)d_in[3];  // [128, 512]
    const float* c = (const float*)d_in[4];  // [512, 128]
    float* out = (float*)d_out;              // x_new [65536*512] then output [65536*128]

    cudaFuncSetAttribute(rnn_kernel, cudaFuncAttributeMaxDynamicSharedMemorySize, SMEM_BYTES);
    rnn_kernel<<<BATCH / BM, NT, SMEM_BYTES>>>(x, u, a, b, c, out);
}

// round 5
// speedup vs baseline: 1.0518x; 1.0518x over previous
#include <cuda_runtime.h>
#include <cstdint>

// ---------------------------------------------------------------------------
// Warp-specialized tf32 mma.sync kernel (family-portable sm_103 PTX).
// Producer warps 0-7: GEMM1 (u@b chunk) + epilogue (x_new = T1 + decay*x).
// Consumer warps 8-15: GEMM2 (Out += x_new @ c chunk), overlapped one chunk
// behind via named-barrier full/empty handshake on a single x_new stage.
// b, c, decay are preconverted/preswizzled once by prep kernels.
// ---------------------------------------------------------------------------

static constexpr int BATCH = 65536;
static constexpr int DH = 512;
static constexpr int DI = 128;
static constexpr int DO = 128;
static constexpr int BM = 128;
static constexpr int NT = 512;    // 16 warps: 8 producer + 8 consumer
static constexpr int NCH = 8;     // h-chunks of 64

// SMEM float offsets (231424 B total)
static constexpr int U_OFF  = 0;      // u tile [128m x 128k] tf32 (64KB)
static constexpr int B_OFF0 = 16384;  // b chunk [128k x 64n] (32KB)
static constexpr int B_OFF1 = 24576;
static constexpr int C_OFF0 = 32768;  // c chunk [64k x 128n] (32KB)
static constexpr int C_OFF1 = 40960;
static constexpr int XN_OFF = 49152;  // x_new stage [128m x 64k] (32KB)
static constexpr int DEC_OFF = 57344; // decay[512] fp32
static constexpr int SMEM_BYTES = 57856 * 4;

__device__ float g_decay[512];
__device__ float g_bt[65536];   // tf32 bits, preswizzled [8ch][128k x 64n]
__device__ float g_ct[65536];   // tf32 bits, preswizzled [8ch][64k x 128n]

__device__ __forceinline__ uint32_t f2tf(float f) {
    uint32_t r;
    asm("cvt.rna.tf32.f32 %0, %1;" : "=r"(r) : "f"(f));
    return r;
}
__device__ __forceinline__ uint32_t smem_u32(const void* p) {
    uint32_t a;
    asm("{ .reg .u64 t; cvta.to.shared.u64 t, %1; cvt.u32.u64 %0, t; }" : "=r"(a) : "l"(p));
    return a;
}
__device__ __forceinline__ void cpa16(uint32_t d, const void* s) {
    asm volatile("cp.async.cg.shared.global [%0], [%1], 16;" :: "r"(d), "l"(s));
}
#define CP_COMMIT() asm volatile("cp.async.commit_group;" ::: "memory")
#define CP_WAIT(n)  asm volatile("cp.async.wait_group %0;" :: "n"(n) : "memory")
#define BAR_SYNC(id, cnt) asm volatile("bar.sync %0, %1;" :: "n"(id), "n"(cnt) : "memory")
#define BAR_ARRIVE(id, cnt) asm volatile("bar.arrive %0, %1;" :: "n"(id), "n"(cnt) : "memory")
// ids: 1 = producer-internal, 2 = consumer-internal, 3 = xn full, 4 = xn empty

__device__ __forceinline__ void mma8(float* c, const uint32_t* a, uint32_t b0, uint32_t b1) {
    asm volatile(
        "mma.sync.aligned.m16n8k8.row.col.f32.tf32.tf32.f32 "
        "{%0,%1,%2,%3}, {%4,%5,%6,%7}, {%8,%9}, {%0,%1,%2,%3};"
        : "+f"(c[0]), "+f"(c[1]), "+f"(c[2]), "+f"(c[3])
        : "r"(a[0]), "r"(a[1]), "r"(a[2]), "r"(a[3]), "r"(b0), "r"(b1));
}

// ---------------- prep kernels (run once per launch, ~3us) ----------------
__global__ void prep_decay(const float* __restrict__ A) {
    __shared__ float red[512];
    int t = threadIdx.x;
    float a = A[t];
    red[t] = a;
    __syncthreads();
    for (int o = 256; o > 0; o >>= 1) {
        if (t < o) red[t] = fmaxf(red[t], red[t + o]);
        __syncthreads();
    }
    float mx = red[0];
    __syncthreads();
    float e = expf(a - mx);
    red[t] = e;
    __syncthreads();
    for (int o = 256; o > 0; o >>= 1) {
        if (t < o) red[t] += red[t + o];
        __syncthreads();
    }
    g_decay[t] = e / red[0];
}

__global__ void prep_bc(const float* __restrict__ B, const float* __restrict__ C) {
    int i = blockIdx.x * 256 + threadIdx.x;  // [0, 16384) float4 units
    int ch = i >> 11, rem = i & 2047;
    {
        int k = rem >> 4, j = rem & 15;
        float4 v = *(const float4*)(B + (size_t)k * DH + ch * 64 + 4 * j);
        int d = ch * 8192 + k * 64 + ((j ^ ((k & 3) << 1)) << 2);
        uint4 w = make_uint4(f2tf(v.x), f2tf(v.y), f2tf(v.z), f2tf(v.w));
        *(uint4*)&g_bt[d] = w;
    }
    {
        int h = rem >> 5, j = rem & 31;
        float4 v = *(const float4*)(C + (size_t)(ch * 64 + h) * DO + 4 * j);
        int d = ch * 8192 + h * 128 + ((j ^ ((h & 3) << 1)) << 2);
        uint4 w = make_uint4(f2tf(v.x), f2tf(v.y), f2tf(v.z), f2tf(v.w));
        *(uint4*)&g_ct[d] = w;
    }
}

// ------------------------------- main kernel -------------------------------
__global__ void __launch_bounds__(NT, 1)
rnn_kernel(const float* __restrict__ X, const float* __restrict__ U,
           float* __restrict__ OUT) {
    extern __shared__ float sm[];
    const int tid = threadIdx.x, wid = tid >> 5, lid = tid & 31;
    const int q = lid & 3, r = lid >> 2;
    const int row0 = (int)blockIdx.x * BM;
    const uint32_t smb = smem_u32(sm);

    if (wid < 8) {
        // ===================== PRODUCER (warps 0-7) =====================
        const int pt = tid;  // 0-255
        const int mb1 = (wid >> 1) * 32, nb1 = (wid & 1) * 32;  // GEMM1 tile 32x32

        // prologue: U + decay + b0 (group), b1 (group)
        {
            const float* ug = U + (size_t)row0 * DI;
            #pragma unroll
            for (int it = 0; it < 16; ++it) {
                int i = it * 256 + pt;
                int m = i >> 5, j = i & 31;
                uint32_t dst = smb + (uint32_t)(U_OFF + m * 128 + ((j ^ (m & 7)) << 2)) * 4u;
                cpa16(dst, ug + i * 4);
            }
            if (pt < 128)
                cpa16(smb + (uint32_t)(DEC_OFF + pt * 4) * 4u, g_decay + pt * 4);
            #pragma unroll
            for (int it = 0; it < 8; ++it) {
                int i = it * 256 + pt;
                cpa16(smb + (uint32_t)(B_OFF0 + i * 4) * 4u, g_bt + i * 4);
            }
            CP_COMMIT();
            #pragma unroll
            for (int it = 0; it < 8; ++it) {
                int i = it * 256 + pt;
                cpa16(smb + (uint32_t)(B_OFF1 + i * 4) * 4u, g_bt + 8192 + i * 4);
            }
            CP_COMMIT();
        }
        CP_WAIT(1);
        BAR_SYNC(1, 256);
        // convert U to tf32 in place
        for (int i = pt * 4; i < 16384; i += 1024) {
            float4 v = *(float4*)&sm[U_OFF + i];
            *(uint4*)&sm[U_OFF + i] = make_uint4(f2tf(v.x), f2tf(v.y), f2tf(v.z), f2tf(v.w));
        }
        BAR_SYNC(1, 256);

        for (int ch = 0; ch < NCH; ++ch) {
            const int bo = (ch & 1) ? B_OFF1 : B_OFF0;
            const int hbase = ch * 64;
            CP_WAIT(1);
            BAR_SYNC(1, 256);  // b(ch) visible to all producer warps

            // ---- GEMM1: acc1 = u[128x128] @ b_chunk[128x64], tile 32x32 ----
            float acc1[2][4][4];
            #pragma unroll
            for (int a = 0; a < 2; ++a)
                #pragma unroll
                for (int b2 = 0; b2 < 4; ++b2)
                    #pragma unroll
                    for (int c2 = 0; c2 < 4; ++c2) acc1[a][b2][c2] = 0.f;
            {
                const uint32_t* su = (const uint32_t*)(sm + U_OFF);
                const uint32_t* sb = (const uint32_t*)(sm + bo);
                #pragma unroll
                for (int ks = 0; ks < 16; ++ks) {
                    const int k0 = ks * 8 + q;
                    uint32_t af[2][4], bf[4][2];
                    #pragma unroll
                    for (int tm = 0; tm < 2; ++tm) {
                        const int m = mb1 + tm * 16 + r;
                        const int kx = (m & 7) << 2;
                        af[tm][0] = su[m * 128 + (k0 ^ kx)];
                        af[tm][1] = su[(m + 8) * 128 + (k0 ^ kx)];
                        af[tm][2] = su[m * 128 + ((k0 + 4) ^ kx)];
                        af[tm][3] = su[(m + 8) * 128 + ((k0 + 4) ^ kx)];
                    }
                    const int nx = (k0 & 3) << 3;
                    #pragma unroll
                    for (int tn = 0; tn < 4; ++tn) {
                        const int n = nb1 + tn * 8 + r;
                        bf[tn][0] = sb[k0 * 64 + (n ^ nx)];
                        bf[tn][1] = sb[(k0 + 4) * 64 + (n ^ nx)];
                    }
                    #pragma unroll
                    for (int tm = 0; tm < 2; ++tm)
                        #pragma unroll
                        for (int tn = 0; tn < 4; ++tn)
                            mma8(acc1[tm][tn], af[tm], bf[tn][0], bf[tn][1]);
                }
            }

            BAR_SYNC(4, 512);  // wait: consumer finished reading xn(ch-1)

            // b(ch) buffer now unreferenced by any producer -> prefetch b(ch+2)
            if (ch + 2 < NCH) {
                #pragma unroll
                for (int it = 0; it < 8; ++it) {
                    int i = it * 256 + pt;
                    cpa16(smb + (uint32_t)(bo + i * 4) * 4u,
                          g_bt + (ch + 2) * 8192 + i * 4);
                }
            }
            CP_COMMIT();

            // ---- epilogue: x_new = acc1 + decay*x ; STG ; stage tf32 xn ----
            {
                const float* dec = sm + DEC_OFF + hbase;
                uint32_t* xs = (uint32_t*)(sm + XN_OFF);
                #pragma unroll
                for (int tm = 0; tm < 2; ++tm) {
                    #pragma unroll
                    for (int half = 0; half < 2; ++half) {
                        const int mloc = mb1 + tm * 16 + half * 8 + r;
                        const size_t grow = (size_t)(row0 + mloc);
                        const float* xr = X + grow * DH + hbase;
                        float* yr = OUT + grow * DH + hbase;
                        const int kx = (mloc & 7) << 2;
                        #pragma unroll
                        for (int tn = 0; tn < 4; ++tn) {
                            const int col = nb1 + tn * 8 + 2 * q;
                            float2 xv = *(const float2*)(xr + col);
                            float2 dv = *(const float2*)(dec + col);
                            float v0 = acc1[tm][tn][half * 2 + 0] + dv.x * xv.x;
                            float v1 = acc1[tm][tn][half * 2 + 1] + dv.y * xv.y;
                            *(float2*)(yr + col) = make_float2(v0, v1);
                            *(uint2*)&xs[mloc * 64 + (col ^ kx)] =
                                make_uint2(f2tf(v0), f2tf(v1));
                        }
                    }
                }
            }
            __threadfence_block();
            BAR_ARRIVE(3, 512);  // signal: xn(ch) full
        }
    } else {
        // ===================== CONSUMER (warps 8-15) =====================
        const int ct = tid - 256;  // 0-255
        const int cw = wid - 8;
        const int mb2 = (cw >> 1) * 32, nb2 = (cw & 1) * 64;  // GEMM2 tile 32x64

        // prologue: c0 (group), c1 (group)
        #pragma unroll
        for (int pf = 0; pf < 2; ++pf) {
            const int co = pf ? C_OFF1 : C_OFF0;
            #pragma unroll
            for (int it = 0; it < 8; ++it) {
                int i = it * 256 + ct;
                cpa16(smb + (uint32_t)(co + i * 4) * 4u, g_ct + pf * 8192 + i * 4);
            }
            CP_COMMIT();
        }
        BAR_ARRIVE(4, 512);  // initial: xn empty

        float acc2[2][8][4];
        #pragma unroll
        for (int a = 0; a < 2; ++a)
            #pragma unroll
            for (int b2 = 0; b2 < 8; ++b2)
                #pragma unroll
                for (int c2 = 0; c2 < 4; ++c2) acc2[a][b2][c2] = 0.f;

        for (int ch = 0; ch < NCH; ++ch) {
            const int co = (ch & 1) ? C_OFF1 : C_OFF0;
            CP_WAIT(1);
            BAR_SYNC(2, 256);   // c(ch) visible to all consumer warps
            BAR_SYNC(3, 512);   // wait: xn(ch) full

            // ---- GEMM2: acc2 += x_new_chunk[128x64] @ c_chunk[64x128] ----
            {
                const uint32_t* sx = (const uint32_t*)(sm + XN_OFF);
                const uint32_t* sc = (const uint32_t*)(sm + co);
                #pragma unroll
                for (int ks = 0; ks < 8; ++ks) {
                    const int k0 = ks * 8 + q;
                    uint32_t af[2][4];
                    #pragma unroll
                    for (int tm = 0; tm < 2; ++tm) {
                        const int m = mb2 + tm * 16 + r;
                        const int kx = (m & 7) << 2;
                        af[tm][0] = sx[m * 64 + (k0 ^ kx)];
                        af[tm][1] = sx[(m + 8) * 64 + (k0 ^ kx)];
                        af[tm][2] = sx[m * 64 + ((k0 + 4) ^ kx)];
                        af[tm][3] = sx[(m + 8) * 64 + ((k0 + 4) ^ kx)];
                    }
                    const int nx = (k0 & 3) << 3;
                    #pragma unroll
                    for (int tn = 0; tn < 8; ++tn) {
                        const int n = nb2 + tn * 8 + r;
                        uint32_t b0 = sc[k0 * 128 + (n ^ nx)];
                        uint32_t b1 = sc[(k0 + 4) * 128 + (n ^ nx)];
                        mma8(acc2[0][tn], af[0], b0, b1);
                        mma8(acc2[1][tn], af[1], b0, b1);
                    }
                }
            }
            __threadfence_block();
            BAR_ARRIVE(4, 512);  // signal: xn empty
            BAR_SYNC(2, 256);    // all consumers done reading c(ch)
            if (ch + 2 < NCH) {
                #pragma unroll
                for (int it = 0; it < 8; ++it) {
                    int i = it * 256 + ct;
                    cpa16(smb + (uint32_t)(co + i * 4) * 4u,
                          g_ct + (ch + 2) * 8192 + i * 4);
                }
            }
            CP_COMMIT();
        }

        // ---- final write: Out ----
        float* ob = OUT + (size_t)BATCH * DH;
        #pragma unroll
        for (int tm = 0; tm < 2; ++tm) {
            #pragma unroll
            for (int half = 0; half < 2; ++half) {
                const int mloc = mb2 + tm * 16 + half * 8 + r;
                float* orow = ob + (size_t)(row0 + mloc) * DO;
                #pragma unroll
                for (int tn = 0; tn < 8; ++tn) {
                    const int col = nb2 + tn * 8 + 2 * q;
                    *(float2*)(orow + col) =
                        make_float2(acc2[tm][tn][half * 2], acc2[tm][tn][half * 2 + 1]);
                }
            }
        }
    }
}

extern "C" void kernel_launch(void* const* d_in, const int* in_sizes, int n_in,
                              void* d_out, int out_size) {
    const float* x = (const float*)d_in[0];  // [65536, 512]
    const float* u = (const float*)d_in[1];  // [65536, 128]
    const float* a = (const float*)d_in[2];  // [512]
    const float* b = (const float*)d_in[3];  // [128, 512]
    const float* c = (const float*)d_in[4];  // [512, 128]
    float* out = (float*)d_out;

    prep_decay<<<1, 512>>>(a);
    prep_bc<<<64, 256>>>(b, c);
    cudaFuncSetAttribute(rnn_kernel, cudaFuncAttributeMaxDynamicSharedMemorySize, SMEM_BYTES);
    rnn_kernel<<<BATCH / BM, NT, SMEM_BYTES>>>(x, u, out);
}